// round 6
// baseline (speedup 1.0000x reference)
#include <cuda_runtime.h>
#include <cuda_fp16.h>
#include <stdint.h>

// ---------------------------------------------------------------------------
// TopK Router via warp-specialized HMMA fp16x3 split GEMM.
// logits = x @ W^T : [16384, 64], softmax, top-2.
// x: [4,4096,4096] f32   W: [64,4096] f32
// out f32: probs[16384*64] ++ indices[16384*2] ++ values[16384*2]
// warps 0-3: consumers (32 rows each). warps 4-7: producers.
// R6: MMA emission re-ordered into 3 passes/k-step to kill accumulator RAW stalls.
// ---------------------------------------------------------------------------

#define D_DIM   4096
#define E_DIM   64
#define NROWS   16384
#define ROWS_PER_BLK 128
#define THREADS 256
#define KC      64
#define NCHUNK  (D_DIM / KC)

// smem layout (bytes)
#define A_TILE    (ROWS_PER_BLK * 128)       // 16384 B : 128 rows x 64 k fp16
#define SM_AHI(b) ((b) * 2 * A_TILE)
#define SM_ALO(b) ((b) * 2 * A_TILE + A_TILE)
#define SM_W      (4 * A_TILE)               // 65536
#define W_TILE    (E_DIM * 128)              // 8192 B : 64 e x 64 k fp16
#define SM_WHI(s) (SM_W + (s) * 2 * W_TILE)
#define SM_WLO(s) (SM_W + (s) * 2 * W_TILE + W_TILE)
#define SMEM_BYTES (SM_W + 6 * W_TILE)       // 114688

#define LG_STRIDE 68

#define SWZ(o) ((o) ^ (((o) >> 3) & 0x70))

__device__ __half g_Whi[E_DIM * D_DIM];
__device__ __half g_Wlo[E_DIM * D_DIM];

// ---------------- PTX helpers -----------------------------------------------
__device__ __forceinline__ void cp16(uint32_t dst, const void* src) {
    asm volatile("cp.async.cg.shared.global [%0], [%1], 16;" :: "r"(dst), "l"(src));
}
__device__ __forceinline__ void cp_commit() {
    asm volatile("cp.async.commit_group;");
}
__device__ __forceinline__ void cp_wait1() {
    asm volatile("cp.async.wait_group 1;" ::: "memory");
}
__device__ __forceinline__ void cp_wait0() {
    asm volatile("cp.async.wait_group 0;" ::: "memory");
}
__device__ __forceinline__ void ldsm4(uint32_t addr, uint32_t* r) {
    asm volatile("ldmatrix.sync.aligned.m8n8.x4.shared.b16 {%0,%1,%2,%3}, [%4];"
                 : "=r"(r[0]), "=r"(r[1]), "=r"(r[2]), "=r"(r[3]) : "r"(addr));
}
__device__ __forceinline__ void mma16816(float* c,
                                         const uint32_t* a,
                                         uint32_t b0, uint32_t b1) {
    asm volatile(
        "mma.sync.aligned.m16n8k16.row.col.f32.f16.f16.f32 "
        "{%0,%1,%2,%3}, {%4,%5,%6,%7}, {%8,%9}, {%0,%1,%2,%3};"
        : "+f"(c[0]), "+f"(c[1]), "+f"(c[2]), "+f"(c[3])
        : "r"(a[0]), "r"(a[1]), "r"(a[2]), "r"(a[3]), "r"(b0), "r"(b1));
}

// ---------------- W prep kernel ----------------------------------------------
__global__ void prep_W(const float* __restrict__ W) {
    int i = blockIdx.x * blockDim.x + threadIdx.x;
    float v = W[i] * 64.0f;
    __half h = __float2half_rn(v);
    g_Whi[i] = h;
    g_Wlo[i] = __float2half_rn(v - __half2float(h));
}

// ---------------- producer helpers -------------------------------------------
__device__ __forceinline__ void ldg_chunk(float R[8][8], const float* __restrict__ x,
                                          int row0, int c0, int pt) {
#pragma unroll
    for (int it = 0; it < 8; ++it) {
        int id = it * 128 + pt;
        int row = id >> 3, g = id & 7;
        const float4* p = (const float4*)(x + (size_t)(row0 + row) * D_DIM + c0 + g * 8);
        float4 a = p[0], b = p[1];
        R[it][0]=a.x; R[it][1]=a.y; R[it][2]=a.z; R[it][3]=a.w;
        R[it][4]=b.x; R[it][5]=b.y; R[it][6]=b.z; R[it][7]=b.w;
    }
}
__device__ __forceinline__ void convert_chunk(const float R[8][8], char* smem,
                                              int buf, int pt) {
#pragma unroll
    for (int it = 0; it < 8; ++it) {
        int id = it * 128 + pt;
        int row = id >> 3, g = id & 7;
        uint32_t hv[4], lv[4];
#pragma unroll
        for (int j = 0; j < 4; ++j) {
            float v0 = R[it][2*j]     * 16.0f;
            float v1 = R[it][2*j + 1] * 16.0f;
            __half2 hh = __floats2half2_rn(v0, v1);
            float2 hf  = __half22float2(hh);
            __half2 ll = __floats2half2_rn(v0 - hf.x, v1 - hf.y);
            hv[j] = *reinterpret_cast<uint32_t*>(&hh);
            lv[j] = *reinterpret_cast<uint32_t*>(&ll);
        }
        uint32_t off = SWZ(row * 128 + g * 16);
        *(uint4*)(smem + SM_AHI(buf) + off) = make_uint4(hv[0], hv[1], hv[2], hv[3]);
        *(uint4*)(smem + SM_ALO(buf) + off) = make_uint4(lv[0], lv[1], lv[2], lv[3]);
    }
}
__device__ __forceinline__ void cpW_chunk(uint32_t sbase, int c, int pt) {
    const int slot = c % 3;
#pragma unroll
    for (int it = 0; it < 8; ++it) {
        int id = it * 128 + pt;
        int split = id >> 9;
        int wi = id & 511;
        int e = wi >> 3, q = wi & 7;
        uint32_t dst = sbase + (split ? SM_WLO(slot) : SM_WHI(slot)) + SWZ(e * 128 + q * 16);
        const __half* src = (split ? g_Wlo : g_Whi) + (size_t)e * D_DIM + c * KC + q * 8;
        cp16(dst, src);
    }
    cp_commit();
}

// ---------------- main kernel -------------------------------------------------
__global__ void __launch_bounds__(THREADS, 1)
router_kernel(const float* __restrict__ x, float* __restrict__ out)
{
    extern __shared__ char smem[];
    const int t    = threadIdx.x;
    const int lane = t & 31;
    const int row0 = blockIdx.x * ROWS_PER_BLK;
    const uint32_t sbase = (uint32_t)__cvta_generic_to_shared(smem);
    const bool consumer = (t < 128);

    const int lg = lane >> 3;
    const int li = lane & 7;

    const int wc = t >> 5;
    float acc[2][8][4];
#pragma unroll
    for (int m = 0; m < 2; ++m)
#pragma unroll
        for (int j = 0; j < 8; ++j)
#pragma unroll
            for (int q = 0; q < 4; ++q) acc[m][j][q] = 0.f;

    uint32_t aoffb[2];
#pragma unroll
    for (int m = 0; m < 2; ++m) {
        int arow = 32 * wc + 16 * m + li + ((lg & 1) ? 8 : 0);
        aoffb[m] = (uint32_t)(arow * 128 + ((lg & 2) ? 16 : 0));
    }
    const int berow = li + ((lg & 2) ? 8 : 0);
    const uint32_t boffb = (uint32_t)(berow * 128 + ((lg & 1) ? 16 : 0));

    const int pt = t - 128;
    float R[8][8];

    // ---- prologue (producers) ----
    if (!consumer) {
        ldg_chunk(R, x, row0, 0, pt);
        cpW_chunk(sbase, 0, pt);
        convert_chunk(R, smem, 0, pt);
        ldg_chunk(R, x, row0, KC, pt);
        cpW_chunk(sbase, 1, pt);
        cp_wait1();
    }
    __syncthreads();

    // ---- main loop ----
    for (int c = 0; c < NCHUNK; ++c) {
        if (consumer) {
            const uint32_t ahi = sbase + SM_AHI(c & 1);
            const uint32_t alo = sbase + SM_ALO(c & 1);
            const uint32_t whi = sbase + SM_WHI(c % 3);
            const uint32_t wlo = sbase + SM_WLO(c % 3);

            uint32_t fw[2][4][2][4];   // [buf][p][hi/lo][4]
#pragma unroll
            for (int p = 0; p < 4; ++p) {
                uint32_t bo = SWZ(boffb + (uint32_t)(p * 16 * 128));
                ldsm4(whi + bo, fw[0][p][0]);
                ldsm4(wlo + bo, fw[0][p][1]);
            }
#pragma unroll
            for (int s = 0; s < 4; ++s) {
                uint32_t fa[2][2][4];
#pragma unroll
                for (int m = 0; m < 2; ++m) {
                    uint32_t ao = SWZ(aoffb[m] + s * 32);
                    ldsm4(ahi + ao, fa[m][0]);
                    ldsm4(alo + ao, fa[m][1]);
                }
                if (s < 3) {
#pragma unroll
                    for (int p = 0; p < 4; ++p) {
                        uint32_t bo = SWZ(boffb + (uint32_t)(p * 16 * 128) + (s + 1) * 32);
                        ldsm4(whi + bo, fw[(s + 1) & 1][p][0]);
                        ldsm4(wlo + bo, fw[(s + 1) & 1][p][1]);
                    }
                }
                // ---- pass 1: A_hi x W_hi (16 MMAs, each acc written once) ----
#pragma unroll
                for (int p = 0; p < 4; ++p) {
                    const uint32_t* bh = fw[s & 1][p][0];
#pragma unroll
                    for (int m = 0; m < 2; ++m) {
                        mma16816(acc[m][2 * p],     fa[m][0], bh[0], bh[1]);
                        mma16816(acc[m][2 * p + 1], fa[m][0], bh[2], bh[3]);
                    }
                }
                // ---- pass 2: A_hi x W_lo ----
#pragma unroll
                for (int p = 0; p < 4; ++p) {
                    const uint32_t* bl = fw[s & 1][p][1];
#pragma unroll
                    for (int m = 0; m < 2; ++m) {
                        mma16816(acc[m][2 * p],     fa[m][0], bl[0], bl[1]);
                        mma16816(acc[m][2 * p + 1], fa[m][0], bl[2], bl[3]);
                    }
                }
                // ---- pass 3: A_lo x W_hi ----
#pragma unroll
                for (int p = 0; p < 4; ++p) {
                    const uint32_t* bh = fw[s & 1][p][0];
#pragma unroll
                    for (int m = 0; m < 2; ++m) {
                        mma16816(acc[m][2 * p],     fa[m][1], bh[0], bh[1]);
                        mma16816(acc[m][2 * p + 1], fa[m][1], bh[2], bh[3]);
                    }
                }
            }
        } else {
            if (c + 1 < NCHUNK) convert_chunk(R, smem, (c + 1) & 1, pt);
            if (c + 2 < NCHUNK) {
                ldg_chunk(R, x, row0, (c + 2) * KC, pt);
                cpW_chunk(sbase, c + 2, pt);
                cp_wait1();
            } else if (c + 1 < NCHUNK) {
                cp_wait0();
            }
        }
        __syncthreads();
    }

    // ---- epilogue ----
    float* lgm = (float*)smem;
    if (consumer) {
        const int r_in = lane >> 2;
        const int col  = 2 * (lane & 3);
        const float sc = 1.0f / 1024.0f;
#pragma unroll
        for (int m = 0; m < 2; ++m) {
            const int rb = 32 * wc + 16 * m + r_in;
#pragma unroll
            for (int j = 0; j < 8; ++j) {
                *(float2*)(lgm + rb * LG_STRIDE + 8 * j + col)
                    = make_float2(acc[m][j][0] * sc, acc[m][j][1] * sc);
                *(float2*)(lgm + (rb + 8) * LG_STRIDE + 8 * j + col)
                    = make_float2(acc[m][j][2] * sc, acc[m][j][3] * sc);
            }
        }
    }
    __syncthreads();

    if (t < ROWS_PER_BLK) {
        float l[64];
#pragma unroll
        for (int j = 0; j < 16; ++j) {
            float4 v = *(const float4*)(lgm + t * LG_STRIDE + 4 * j);
            l[4*j+0] = v.x; l[4*j+1] = v.y; l[4*j+2] = v.z; l[4*j+3] = v.w;
        }

        float mx = l[0];
#pragma unroll
        for (int j = 1; j < 64; ++j) mx = fmaxf(mx, l[j]);

        float v1 = -3.4e38f, v2 = -3.4e38f;
        int   i1 = 0,        i2 = 0;
#pragma unroll
        for (int j = 0; j < 64; ++j) {
            float lj = l[j];
            if (lj > v1)      { v2 = v1; i2 = i1; v1 = lj; i1 = j; }
            else if (lj > v2) { v2 = lj; i2 = j; }
        }

        float p[64], s = 0.f;
#pragma unroll
        for (int j = 0; j < 64; ++j) { p[j] = __expf(l[j] - mx); s += p[j]; }
        float inv = __fdividef(1.0f, s);

        const int grow = row0 + t;
        float* po = out + (size_t)grow * 64;
#pragma unroll
        for (int j = 0; j < 16; ++j) {
            float4 v;
            v.x = p[4*j+0] * inv; v.y = p[4*j+1] * inv;
            v.z = p[4*j+2] * inv; v.w = p[4*j+3] * inv;
            *(float4*)(po + 4 * j) = v;
        }
        float* io = out + (size_t)NROWS * 64;
        io[(size_t)grow * 2 + 0] = (float)i1;
        io[(size_t)grow * 2 + 1] = (float)i2;
        float* vo = out + (size_t)NROWS * 64 + (size_t)NROWS * 2;
        vo[(size_t)grow * 2 + 0] = __expf(v1 - mx) * inv;
        vo[(size_t)grow * 2 + 1] = __expf(v2 - mx) * inv;
    }
}

// ---------------------------------------------------------------------------
extern "C" void kernel_launch(void* const* d_in, const int* in_sizes, int n_in,
                              void* d_out, int out_size) {
    const float* x = (const float*)d_in[0];
    const float* W = (const float*)d_in[1];
    float* out = (float*)d_out;

    prep_W<<<(E_DIM * D_DIM) / 256, 256>>>(W);

    cudaFuncSetAttribute(router_kernel,
                         cudaFuncAttributeMaxDynamicSharedMemorySize, SMEM_BYTES);
    router_kernel<<<NROWS / ROWS_PER_BLK, THREADS, SMEM_BYTES>>>(x, out);
}